// round 11
// baseline (speedup 1.0000x reference)
#include <cuda_runtime.h>
#include <stdint.h>

#define V_N    1024
#define EDGE_N 6144
#define MAXD   64
#define LMAX   40          // per-column cap in scheduler (deg max ~18 expected)
#define PAD    6176        // floats per staged row array: 24704 B, 128B-aligned

// ---- static device scratch (no allocation allowed) ----
__device__ uint16_t g_e2v[EDGE_N];
__device__ __align__(16) int g_deg[V_N];
__device__ __align__(16) uint16_t g_ell[MAXD * V_N];  // column-major: ell[j*V_N + v]
__device__ int g_ctr;                                  // work-queue counter

// K0: reset the work-queue counter (must run every launch — deterministic).
__global__ void k_reset() { g_ctr = 0; }

// K1: sentinel-fill ELL, zero degrees, recover edge->vnode from one-hot mask.
__global__ void k_prep(const uint4* __restrict__ mask4) {
    int stride = gridDim.x * blockDim.x;
    int tid0 = blockIdx.x * blockDim.x + threadIdx.x;
    for (int i = tid0; i < MAXD * V_N; i += stride) g_ell[i] = (uint16_t)EDGE_N;
    for (int i = tid0; i < V_N; i += stride) g_deg[i] = 0;
    for (int i = tid0; i < (EDGE_N * V_N) / 4; i += stride) {
        uint4 m = mask4[i];
        if (m.x | m.y | m.z | m.w) {
            int base = i * 4;
            if (m.x) g_e2v[base >> 10]       = (uint16_t)( base      & (V_N - 1));
            if (m.y) g_e2v[(base + 1) >> 10] = (uint16_t)((base + 1) & (V_N - 1));
            if (m.z) g_e2v[(base + 2) >> 10] = (uint16_t)((base + 2) & (V_N - 1));
            if (m.w) g_e2v[(base + 3) >> 10] = (uint16_t)((base + 3) & (V_N - 1));
        }
    }
}

// K2: one WARP per edge: stable deterministic ELL placement in ascending edge order.
__global__ __launch_bounds__(256) void k_build() {
    __shared__ uint16_t se[EDGE_N];
    int t = threadIdx.x;
    const uint32_t* src = (const uint32_t*)g_e2v;
    uint32_t* dst = (uint32_t*)se;
    #pragma unroll
    for (int i = 0; i < EDGE_N / 2 / 256; ++i)
        dst[i * 256 + t] = src[i * 256 + t];
    __syncthreads();

    int e = (blockIdx.x * blockDim.x + t) >> 5;
    int lane = t & 31;
    if (e < EDGE_N) {
        int v = se[e];
        int cnt = 0;
        for (int i = lane; i < e; i += 32) cnt += (se[i] == v);
        cnt = __reduce_add_sync(0xffffffff, cnt);
        if (lane == 0) {
            g_ell[cnt * V_N + v] = (uint16_t)e;
            atomicAdd(&g_deg[v], 1);
        }
    }
}

// K3: bank scheduler, LOCAL-ARRAY version. In k_main each gather instruction is
// a full-warp LDS.32: lane l of warp w, component k reads edge for vnode
// v = 128w + 4l + k; bank = e & 31. Reorder each vnode's ELL column (fp-add
// reorder is free & deterministic) so every step's 32 lanes hit distinct banks.
// Sentinel (6144) sits on bank 0 -> reserve bank 0 once any lane is idle.
__global__ void k_sched() {
    int g = threadIdx.x;                 // 32 groups: (w,k)
    if (g >= 32) return;
    int w = g >> 2, k = g & 3;

    uint16_t col[32][LMAX];
    int deg[32], v[32];
    int mindeg = MAXD, maxdeg = 0;
    for (int i = 0; i < 32; ++i) {
        v[i] = 128 * w + 4 * i + k;
        int d = g_deg[v[i]]; if (d > LMAX) d = LMAX;
        deg[i] = d;
        mindeg = min(mindeg, d); maxdeg = max(maxdeg, d);
        for (int q = 0; q < d; ++q) col[i][q] = g_ell[q * V_N + v[i]];
    }
    for (int j = 0; j < maxdeg; ++j) {
        unsigned used = (j >= mindeg) ? 1u : 0u;   // reserve sentinel bank 0
        for (int i = 0; i < 32; ++i) {
            if (j >= deg[i]) continue;
            int best = j;
            for (int q = j; q < deg[i]; ++q) {
                unsigned b = col[i][q] & 31u;
                if (!((used >> b) & 1u)) { best = q; break; }
            }
            uint16_t tmp = col[i][j]; col[i][j] = col[i][best]; col[i][best] = tmp;
            used |= 1u << (col[i][j] & 31u);
        }
    }
    for (int i = 0; i < 32; ++i)
        for (int q = 0; q < deg[i]; ++q) g_ell[q * V_N + v[i]] = col[i][q];
}

// ---- cp.async helpers ----
__device__ __forceinline__ void cp16(uint32_t dst, const float4* src) {
    asm volatile("cp.async.cg.shared.global [%0], [%1], 16;" :: "r"(dst), "l"(src));
}
__device__ __forceinline__ void cp_commit() { asm volatile("cp.async.commit_group;"); }
__device__ __forceinline__ void cp_wait1()  { asm volatile("cp.async.wait_group 1;"); }
__device__ __forceinline__ void cp_wait0()  { asm volatile("cp.async.wait_group 0;"); }

// stage 4 rows of group grp (clamped) into buffer buf as 4 LINEAR row arrays
__device__ __forceinline__ void stage_grp(const float* fprev, int grp, int B,
                                          uint32_t sbase, int buf, int t) {
    long long b0 = (long long)grp * 4;
    #pragma unroll
    for (int r = 0; r < 4; ++r) {
        long long b = b0 + r; if (b > B - 1) b = B - 1;
        const float4* src = (const float4*)(fprev + b * EDGE_N);
        uint32_t d = sbase + (uint32_t)((buf * 4 + r) * PAD) * 4u;
        #pragma unroll
        for (int i = 0; i < 6; ++i) {
            int u = i * 256 + t;
            cp16(d + (uint32_t)u * 16u, src + u);
        }
    }
    cp_commit();
}

// Main: persistent, double-buffered. While gathering group g from buffer A,
// cp.async streams group g' into buffer B -> DRAM never idles behind the
// barrier. Work queue via atomicAdd: nondeterministic ASSIGNMENT, but each
// group writes a disjoint output slice with a deterministic value.
__global__ __launch_bounds__(256) void k_main(
    const float* __restrict__ fin, const float* __restrict__ fprev,
    float* __restrict__ out, int B)
{
    extern __shared__ __align__(16) float st[];       // 2*4*PAD floats = 197632 B
    __shared__ int sh_g;
    uint32_t sbase = (uint32_t)__cvta_generic_to_shared(st);
    int t = threadIdx.x;

    if (t < 8) st[t * PAD + EDGE_N] = 0.0f;           // sentinels, never overwritten
    int4 dg = ((const int4*)g_deg)[t];                // thread t owns vnodes 4t..4t+3
    int md = max(max(dg.x, dg.y), max(dg.z, dg.w));
    int ngroups = (B + 3) / 4;

    if (t == 0) sh_g = atomicAdd(&g_ctr, 1);
    __syncthreads();
    int g = sh_g;
    int buf = 0;
    if (g < ngroups) stage_grp(fprev, g, B, sbase, 0, t);

    while (g < ngroups) {
        if (t == 0) sh_g = atomicAdd(&g_ctr, 1);
        __syncthreads();
        int gn = sh_g;
        bool more = (gn < ngroups);
        if (more) stage_grp(fprev, gn, B, sbase, buf ^ 1, t);
        if (more) cp_wait1(); else cp_wait0();
        __syncthreads();                              // buffer `buf` fully staged

        long long b0 = (long long)g * 4;
        long long i1 = (b0 + 1 < B) ? b0 + 1 : B - 1;
        long long i2 = (b0 + 2 < B) ? b0 + 2 : B - 1;
        long long i3 = (b0 + 3 < B) ? b0 + 3 : B - 1;
        float4 s0 = ((const float4*)(fin + b0 * V_N))[t];
        float4 s1 = ((const float4*)(fin + i1 * V_N))[t];
        float4 s2 = ((const float4*)(fin + i2 * V_N))[t];
        float4 s3 = ((const float4*)(fin + i3 * V_N))[t];

        const float* c0 = st + (buf * 4 + 0) * PAD;
        const float* c1 = c0 + PAD;
        const float* c2 = c0 + 2 * PAD;
        const float* c3 = c0 + 3 * PAD;
        const ushort4* ellp = (const ushort4*)g_ell;
        #pragma unroll 2
        for (int j = 0; j < md; ++j) {
            ushort4 e = ellp[j * (V_N / 4) + t];
            s0.x += c0[e.x]; s1.x += c1[e.x]; s2.x += c2[e.x]; s3.x += c3[e.x];
            s0.y += c0[e.y]; s1.y += c1[e.y]; s2.y += c2[e.y]; s3.y += c3[e.y];
            s0.z += c0[e.z]; s1.z += c1[e.z]; s2.z += c2[e.z]; s3.z += c3[e.z];
            s0.w += c0[e.w]; s1.w += c1[e.w]; s2.w += c2[e.w]; s3.w += c3[e.w];
        }

        ((float4*)(out + b0 * V_N))[t] = s0;
        ((float4*)(out + i1 * V_N))[t] = s1;
        ((float4*)(out + i2 * V_N))[t] = s2;
        ((float4*)(out + i3 * V_N))[t] = s3;
        __syncthreads();                              // done reading `buf`
        g = gn; buf ^= 1;
    }
}

extern "C" void kernel_launch(void* const* d_in, const int* in_sizes, int n_in,
                              void* d_out, int out_size) {
    const float* fin   = (const float*)d_in[0];   // [B, V_N]
    const float* fprev = (const float*)d_in[1];   // [B, EDGE_N]
    const float* mask  = (const float*)d_in[2];   // [EDGE_N, V_N]
    int B = in_sizes[0] / V_N;

    static const int kSmem = 2 * 4 * PAD * sizeof(float);   // 197632 B
    cudaFuncSetAttribute(k_main, cudaFuncAttributeMaxDynamicSharedMemorySize, kSmem);

    k_reset<<<1, 1>>>();
    k_prep <<<2048, 256>>>((const uint4*)mask);
    k_build<<<(EDGE_N * 32) / 256, 256>>>();
    k_sched<<<1, 32>>>();
    k_main <<<152, 256, kSmem>>>(fin, fprev, (float*)d_out, B);
}

// round 14
// speedup vs baseline: 1.3244x; 1.3244x over previous
#include <cuda_runtime.h>
#include <stdint.h>

#define V_N    1024
#define EDGE_N 6144
#define MAXD   64
#define LSTEPS 256          // elist rows capacity (worst case 4*63 < 256)
#define PAD    6176         // floats per staged row array (sentinel at 6144)
#define SCHED_ROWS 48       // scheduler smem row capacity (typical Ltot ~26)

// ---- static device scratch (no allocation allowed) ----
__device__ uint16_t g_e2v[EDGE_N];
__device__ __align__(16) int g_deg[V_N];
__device__ __align__(16) uint16_t g_ell[MAXD * V_N];     // column-major per-vnode lists
__device__ __align__(16) uint16_t g_elist[LSTEPS * 256]; // packed per-thread lists
__device__ uint32_t g_Lt[8];                             // per-warp packed L0..L3
__device__ __align__(16) uint16_t g_slotOf[V_N];         // vnode -> slot
__device__ __align__(16) uint16_t g_vOfSlot[V_N];        // slot -> vnode

// K1: sentinel-fill ELL, zero degrees, recover edge->vnode from one-hot mask.
__global__ void k_prep(const uint4* __restrict__ mask4) {
    int stride = gridDim.x * blockDim.x;
    int tid0 = blockIdx.x * blockDim.x + threadIdx.x;
    for (int i = tid0; i < MAXD * V_N; i += stride) g_ell[i] = (uint16_t)EDGE_N;
    for (int i = tid0; i < V_N; i += stride) g_deg[i] = 0;
    for (int i = tid0; i < (EDGE_N * V_N) / 4; i += stride) {
        uint4 m = mask4[i];
        if (m.x | m.y | m.z | m.w) {
            int base = i * 4;
            if (m.x) g_e2v[base >> 10]       = (uint16_t)( base      & (V_N - 1));
            if (m.y) g_e2v[(base + 1) >> 10] = (uint16_t)((base + 1) & (V_N - 1));
            if (m.z) g_e2v[(base + 2) >> 10] = (uint16_t)((base + 2) & (V_N - 1));
            if (m.w) g_e2v[(base + 3) >> 10] = (uint16_t)((base + 3) & (V_N - 1));
        }
    }
}

// K2: one WARP per edge: stable deterministic per-vnode list, ascending edge order.
__global__ __launch_bounds__(256) void k_build() {
    __shared__ uint16_t se[EDGE_N];
    int t = threadIdx.x;
    const uint32_t* src = (const uint32_t*)g_e2v;
    uint32_t* dst = (uint32_t*)se;
    #pragma unroll
    for (int i = 0; i < EDGE_N / 2 / 256; ++i)
        dst[i * 256 + t] = src[i * 256 + t];
    __syncthreads();

    int e = (blockIdx.x * blockDim.x + t) >> 5;
    int lane = t & 31;
    if (e < EDGE_N) {
        int v = se[e];
        int cnt = 0;
        for (int i = lane; i < e; i += 32) cnt += (se[i] == v);
        cnt = __reduce_add_sync(0xffffffff, cnt);
        if (lane == 0 && cnt < MAXD) {
            g_ell[cnt * V_N + v] = (uint16_t)e;
            atomicAdd(&g_deg[v], 1);
        }
    }
}

// K3: deterministic degree-rank (desc) via per-degree bitmasks + popcount.
// rank -> snake slot across 4 degree-quartile bands so each thread's 4 vnodes
// have balanced total degree AND warp lanes see near-equal per-band degrees.
__global__ void k_rank() {                 // 1 block, 1024 threads
    __shared__ unsigned hist[MAXD];
    __shared__ unsigned off[MAXD];
    __shared__ unsigned mask[MAXD][32];
    int v = threadIdx.x;
    if (v < MAXD) hist[v] = 0;
    ((unsigned*)mask)[v] = 0;
    ((unsigned*)mask)[v + 1024] = 0;
    __syncthreads();
    int d = g_deg[v]; if (d > MAXD - 1) d = MAXD - 1;
    atomicAdd(&hist[d], 1);
    atomicOr(&mask[d][v >> 5], 1u << (v & 31));
    __syncthreads();
    if (v == 0) {
        unsigned acc = 0;
        for (int dd = MAXD - 1; dd >= 0; --dd) { off[dd] = acc; acc += hist[dd]; }
    }
    __syncthreads();
    unsigned within = 0;
    int w = v >> 5;
    for (int i = 0; i < w; ++i) within += __popc(mask[d][i]);
    within += __popc(mask[d][w] & ((1u << (v & 31)) - 1u));
    int rank = (int)(off[d] + within);
    int k = rank >> 8, i2 = rank & 255;
    int tt = (k & 1) ? (255 - i2) : i2;    // snake for cross-thread balance
    int slot = (k << 8) | tt;
    g_slotOf[v] = (uint16_t)slot;
    g_vOfSlot[slot] = (uint16_t)v;
}

// K4: pack per-thread segment lists, uniform per-warp segment lengths (warp max).
__global__ __launch_bounds__(256) void k_pack() {
    __shared__ uint8_t sL[8][4];
    int t = threadIdx.x, w = t >> 5;
    int vk[4], dk[4];
    #pragma unroll
    for (int k = 0; k < 4; ++k) {
        int v = g_vOfSlot[(k << 8) | t];
        int d = g_deg[v]; if (d > MAXD) d = MAXD;
        vk[k] = v; dk[k] = d;
        unsigned m = __reduce_max_sync(0xffffffffu, (unsigned)d);
        if ((t & 31) == 0) sL[w][k] = (uint8_t)m;
    }
    __syncthreads();
    uint32_t packed = sL[w][0] | ((uint32_t)sL[w][1] << 8)
                    | ((uint32_t)sL[w][2] << 16) | ((uint32_t)sL[w][3] << 24);
    if ((t & 31) == 0) g_Lt[w] = packed;
    int base = 0;
    #pragma unroll
    for (int k = 0; k < 4; ++k) {
        int Lk = sL[w][k];
        for (int q = 0; q < Lk; ++q) {
            uint16_t e = (q < dk[k]) ? g_ell[q * V_N + vk[k]] : (uint16_t)EDGE_N;
            g_elist[(base + q) * 256 + t] = e;
        }
        base += Lk;
    }
}

// K5: warp-cooperative bank scheduler. For each gather step, the 32 lanes of a
// warp negotiate (match_any bidding) a per-lane list entry whose smem bank
// (e & 31) is distinct; pad lanes broadcast the sentinel on bank 0 (reserved).
// Reorders only within each lane's own segment -> fp-sum reorder, deterministic.
__global__ __launch_bounds__(256) void k_sched() {
    __shared__ uint16_t se[SCHED_ROWS * 256];
    int t = threadIdx.x, w = t >> 5, lane = t & 31;
    uint32_t Lp = g_Lt[w];
    int L0 = Lp & 255, L1 = (Lp >> 8) & 255, L2 = (Lp >> 16) & 255, L3 = (Lp >> 24) & 255;
    int Ltot = L0 + L1 + L2 + L3;
    if (Ltot > SCHED_ROWS) return;         // uniform per warp; perf fallback only

    for (int q = 0; q < Ltot; ++q) se[q * 256 + t] = g_elist[q * 256 + t];
    __syncwarp();

    int basek[4] = {0, L0, L0 + L1, L0 + L1 + L2};
    int fill[4];
    #pragma unroll
    for (int k = 0; k < 4; ++k) {
        int v = g_vOfSlot[(k << 8) | t];
        int d = g_deg[v]; if (d > MAXD) d = MAXD;
        fill[k] = d;
    }

    int k = 0;
    for (int j = 0; j < Ltot; ++j) {
        while (k < 3 && j >= basek[k + 1]) ++k;      // uniform across warp
        int endq = basek[k] + fill[k];
        bool pad = (j >= endq);
        unsigned used = __ballot_sync(0xffffffff, pad) ? 1u : 0u;  // reserve bank 0
        bool committed = pad;
        for (int round = 0; round < 4; ++round) {
            if (!__ballot_sync(0xffffffff, !committed)) break;
            int mypos = -1, mybank = 0, key = 64 + lane;
            bool forced = false;
            if (!committed) {
                for (int q = j; q < endq; ++q) {
                    int b = se[q * 256 + t] & 31;
                    if (!((used >> b) & 1u)) { mypos = q; mybank = b; break; }
                }
                if (mypos < 0) { forced = true; mypos = j; mybank = se[j * 256 + t] & 31; }
                key = mybank;
            }
            unsigned peers = __match_any_sync(0xffffffff, key);
            bool leader = ((int)(__ffs(peers) - 1) == lane);
            bool win = !committed && (leader || forced || round == 3);
            unsigned newbits = __reduce_or_sync(0xffffffff, win ? (1u << mybank) : 0u);
            if (win) {
                uint16_t a = se[j * 256 + t];
                se[j * 256 + t] = se[mypos * 256 + t];
                se[mypos * 256 + t] = a;
                committed = true;
            }
            used |= newbits;
        }
    }
    __syncwarp();
    for (int q = 0; q < Ltot; ++q) g_elist[q * 256 + t] = se[q * 256 + t];
}

// ---- cp.async helpers ----
__device__ __forceinline__ void cp16(uint32_t dst, const float4* src) {
    asm volatile("cp.async.cg.shared.global [%0], [%1], 16;" :: "r"(dst), "l"(src));
}
__device__ __forceinline__ void cp_commit() { asm volatile("cp.async.commit_group;"); }
__device__ __forceinline__ void cp_wait1()  { asm volatile("cp.async.wait_group 1;"); }
__device__ __forceinline__ void cp_wait0()  { asm volatile("cp.async.wait_group 0;"); }

__device__ __forceinline__ void stage_grp(const float* fprev, int grp, int B,
                                          uint32_t sbase, int buf, int t) {
    long long b0 = (long long)grp * 4;
    #pragma unroll
    for (int r = 0; r < 4; ++r) {
        long long b = b0 + r; if (b > B - 1) b = B - 1;
        const float4* src = (const float4*)(fprev + b * EDGE_N);
        uint32_t d = sbase + (uint32_t)((buf * 4 + r) * PAD) * 4u;
        #pragma unroll
        for (int i = 0; i < 6; ++i) {
            int u = i * 256 + t;
            cp16(d + (uint32_t)u * 16u, src + u);
        }
    }
    cp_commit();
}

// Main: persistent, static group partition, cp.async double-buffered linear rows.
// Gather: per-thread packed segment lists (no ELL padding), bank-scheduled
// LDS.32 x4 per edge; accumulators land in smem res[] by slot (coalesced),
// then one scattered res read restores natural vnode order for coalesced output.
__global__ __launch_bounds__(256) void k_main(
    const float* __restrict__ fin, const float* __restrict__ fprev,
    float* __restrict__ out, int B)
{
    extern __shared__ __align__(16) float st[];        // 8*PAD stage + 1024 float4 res
    float4* res = (float4*)(st + 8 * PAD);
    int t = threadIdx.x, w = t >> 5;
    uint32_t sbase = (uint32_t)__cvta_generic_to_shared(st);

    if (t < 8) st[t * PAD + EDGE_N] = 0.0f;            // sentinels, never overwritten
    uint32_t Lp = g_Lt[w];
    ushort4 slots = ((const ushort4*)g_slotOf)[t];

    int ngroups = (B + 3) / 4;
    int per = ngroups / gridDim.x, rem = ngroups % gridDim.x;
    int bid = blockIdx.x;
    int g_lo = bid * per + min(bid, rem);
    int g_hi = g_lo + per + (bid < rem ? 1 : 0);
    if (g_lo >= g_hi) return;

    int buf = 0;
    stage_grp(fprev, g_lo, B, sbase, 0, t);
    for (int g = g_lo; g < g_hi; ++g) {
        bool more = (g + 1 < g_hi);
        if (more) stage_grp(fprev, g + 1, B, sbase, buf ^ 1, t);
        if (more) cp_wait1(); else cp_wait0();
        __syncthreads();

        const float* c0 = st + (buf * 4 + 0) * PAD;
        const float* c1 = c0 + PAD;
        const float* c2 = c0 + 2 * PAD;
        const float* c3 = c0 + 3 * PAD;
        int p = 0;
        #pragma unroll
        for (int k = 0; k < 4; ++k) {
            int Lk = (Lp >> (8 * k)) & 255;
            float4 s = make_float4(0.f, 0.f, 0.f, 0.f);
            #pragma unroll 2
            for (int j = 0; j < Lk; ++j) {
                int e = g_elist[p * 256 + t]; ++p;
                s.x += c0[e]; s.y += c1[e]; s.z += c2[e]; s.w += c3[e];
            }
            res[(k << 8) | t] = s;
        }
        __syncthreads();

        long long b0 = (long long)g * 4;
        long long r1 = b0 + 1 < B ? b0 + 1 : B - 1;
        long long r2 = b0 + 2 < B ? b0 + 2 : B - 1;
        long long r3 = b0 + 3 < B ? b0 + 3 : B - 1;
        float4 q0 = res[slots.x], q1 = res[slots.y], q2 = res[slots.z], q3 = res[slots.w];
        float4 f0 = ((const float4*)(fin + b0 * V_N))[t];
        float4 f1 = ((const float4*)(fin + r1 * V_N))[t];
        float4 f2 = ((const float4*)(fin + r2 * V_N))[t];
        float4 f3 = ((const float4*)(fin + r3 * V_N))[t];
        ((float4*)(out + b0 * V_N))[t] = make_float4(q0.x + f0.x, q1.x + f0.y, q2.x + f0.z, q3.x + f0.w);
        ((float4*)(out + r1 * V_N))[t] = make_float4(q0.y + f1.x, q1.y + f1.y, q2.y + f1.z, q3.y + f1.w);
        ((float4*)(out + r2 * V_N))[t] = make_float4(q0.z + f2.x, q1.z + f2.y, q2.z + f2.z, q3.z + f2.w);
        ((float4*)(out + r3 * V_N))[t] = make_float4(q0.w + f3.x, q1.w + f3.y, q2.w + f3.z, q3.w + f3.w);
        __syncthreads();                               // done with buf & res
        buf ^= 1;
    }
}

extern "C" void kernel_launch(void* const* d_in, const int* in_sizes, int n_in,
                              void* d_out, int out_size) {
    const float* fin   = (const float*)d_in[0];   // [B, V_N]
    const float* fprev = (const float*)d_in[1];   // [B, EDGE_N]
    const float* mask  = (const float*)d_in[2];   // [EDGE_N, V_N]
    int B = in_sizes[0] / V_N;

    static const int kSmem = 8 * PAD * sizeof(float) + V_N * sizeof(float4); // 214016
    cudaFuncSetAttribute(k_main, cudaFuncAttributeMaxDynamicSharedMemorySize, kSmem);

    k_prep <<<2048, 256>>>((const uint4*)mask);
    k_build<<<(EDGE_N * 32) / 256, 256>>>();
    k_rank <<<1, 1024>>>();
    k_pack <<<1, 256>>>();
    k_sched<<<1, 256>>>();
    k_main <<<148, 256, kSmem>>>(fin, fprev, (float*)d_out, B);
}

// round 15
// speedup vs baseline: 1.4067x; 1.0621x over previous
#include <cuda_runtime.h>
#include <stdint.h>

#define V_N    1024
#define EDGE_N 6144
#define MAXD   64
#define LMAX2  24            // scheduler per-column capacity (deg max ~18 expected)

// ---- static device scratch (no allocation allowed) ----
__device__ uint16_t g_e2v[EDGE_N];
__device__ __align__(16) int g_deg[V_N];
__device__ __align__(16) uint16_t g_ell[MAXD * V_N];   // column-major: ell[j*V_N + v]

// swizzle: bijective, touches bits 0-2 only (6144 = 0x1800 unaffected),
// makes the staging STS.128 pattern conflict-free across 8-lane phases.
__device__ __forceinline__ int swz(int e) { return e ^ ((e >> 2) & 7); }

// K1: sentinel-fill ELL, zero degrees, recover edge->vnode from one-hot mask.
__global__ void k_prep(const uint4* __restrict__ mask4) {
    int stride = gridDim.x * blockDim.x;
    int tid0 = blockIdx.x * blockDim.x + threadIdx.x;
    for (int i = tid0; i < MAXD * V_N; i += stride) g_ell[i] = (uint16_t)EDGE_N;
    for (int i = tid0; i < V_N; i += stride) g_deg[i] = 0;
    for (int i = tid0; i < (EDGE_N * V_N) / 4; i += stride) {
        uint4 m = mask4[i];
        if (m.x | m.y | m.z | m.w) {
            int base = i * 4;
            if (m.x) g_e2v[base >> 10]       = (uint16_t)( base      & (V_N - 1));
            if (m.y) g_e2v[(base + 1) >> 10] = (uint16_t)((base + 1) & (V_N - 1));
            if (m.z) g_e2v[(base + 2) >> 10] = (uint16_t)((base + 2) & (V_N - 1));
            if (m.w) g_e2v[(base + 3) >> 10] = (uint16_t)((base + 3) & (V_N - 1));
        }
    }
}

// K2: one WARP per edge: stable deterministic ELL placement, ascending edge order.
__global__ __launch_bounds__(256) void k_build() {
    __shared__ uint16_t se[EDGE_N];
    int t = threadIdx.x;
    const uint32_t* src = (const uint32_t*)g_e2v;
    uint32_t* dst = (uint32_t*)se;
    #pragma unroll
    for (int i = 0; i < EDGE_N / 2 / 256; ++i)
        dst[i * 256 + t] = src[i * 256 + t];
    __syncthreads();

    int e = (blockIdx.x * blockDim.x + t) >> 5;
    int lane = t & 31;
    if (e < EDGE_N) {
        int v = se[e];
        int cnt = 0;
        for (int i = lane; i < e; i += 32) cnt += (se[i] == v);
        cnt = __reduce_add_sync(0xffffffff, cnt);
        if (lane == 0 && cnt < MAXD) {
            g_ell[cnt * V_N + v] = (uint16_t)e;
            atomicAdd(&g_deg[v], 1);
        }
    }
}

// K3: bank-group scheduler, SMEM-resident (R8's algorithm, 15x cheaper memory).
// k_main gather: LDS.128 phase p of warp w, component k covers vnodes
// v(i) = 64w + 16p + 2i + k (i=0..7); bank-group = swz(e) & 7. Reorder each
// vnode's ELL column (fp-add reorder, deterministic) so the 8 edges of every
// step hit distinct groups. Sentinel (6144) sits on group 0 -> reserve group 0
// once any lane in the phase pads (j >= its deg).
__global__ __launch_bounds__(128) void k_sched() {
    __shared__ uint16_t col[128][8][LMAX2];            // 49152 B
    int g = threadIdx.x;                               // 128 groups
    int w = g >> 3, k = (g >> 2) & 1, p = g & 3;

    int v[8], deg[8];
    int mindeg = MAXD, maxdeg = 0;
    bool ok = true;
    #pragma unroll
    for (int i = 0; i < 8; ++i) {
        v[i] = 64 * w + 16 * p + 2 * i + k;
        int d = g_deg[v[i]];
        if (d > LMAX2) { ok = false; d = LMAX2; }
        deg[i] = d;
        mindeg = min(mindeg, d); maxdeg = max(maxdeg, d);
    }
    if (!ok) return;                                   // perf fallback only

    for (int i = 0; i < 8; ++i)
        for (int q = 0; q < deg[i]; ++q)
            col[g][i][q] = g_ell[q * V_N + v[i]];

    for (int j = 0; j < maxdeg; ++j) {
        unsigned used = (j >= mindeg) ? 1u : 0u;       // reserve sentinel group 0
        for (int i = 0; i < 8; ++i) {
            if (j >= deg[i]) continue;
            int best = j;
            for (int q = j; q < deg[i]; ++q) {
                unsigned b = (unsigned)(swz(col[g][i][q]) & 7);
                if (!((used >> b) & 1u)) { best = q; break; }
            }
            uint16_t tmp = col[g][i][j];
            col[g][i][j] = col[g][i][best];
            col[g][i][best] = tmp;
            used |= 1u << (swz(col[g][i][j]) & 7);
        }
    }

    for (int i = 0; i < 8; ++i)
        for (int q = 0; q < deg[i]; ++q)
            g_ell[q * V_N + v[i]] = col[g][i][q];
}

// Main: one 512-thread block per FOUR batch rows, 2 blocks/SM (32 warps/SM).
// stage[swz(e)] = float4{r0[e],r1[e],r2[e],r3[e]}; thread t owns vnodes 2t,2t+1;
// per step: ushort2 index (coalesced, L1-resident) + 2 scheduled LDS.128 + 2
// vector FADD4. Sentinel stage[6144]=0 makes per-thread ELL padding branch-free.
__global__ __launch_bounds__(512, 2) void k_main(
    const float* __restrict__ fin, const float* __restrict__ fprev,
    float* __restrict__ out, int B)
{
    extern __shared__ __align__(16) float4 stage[];    // 6145 float4 = 98320 B
    int t = threadIdx.x;
    long long b0 = (long long)blockIdx.x * 4;
    long long i1 = (b0 + 1 < B) ? b0 + 1 : b0;
    long long i2 = (b0 + 2 < B) ? b0 + 2 : b0;
    long long i3 = (b0 + 3 < B) ? b0 + 3 : b0;

    const float4* r0 = (const float4*)(fprev + b0 * EDGE_N);
    const float4* r1 = (const float4*)(fprev + i1 * EDGE_N);
    const float4* r2 = (const float4*)(fprev + i2 * EDGE_N);
    const float4* r3 = (const float4*)(fprev + i3 * EDGE_N);
    #pragma unroll
    for (int i = 0; i < 3; ++i) {                      // 3*512 = 1536 float4/row
        int u = i * 512 + t;
        float4 a = r0[u], b = r1[u], c = r2[u], d = r3[u];
        int base = u * 4;
        stage[swz(base + 0)] = make_float4(a.x, b.x, c.x, d.x);
        stage[swz(base + 1)] = make_float4(a.y, b.y, c.y, d.y);
        stage[swz(base + 2)] = make_float4(a.z, b.z, c.z, d.z);
        stage[swz(base + 3)] = make_float4(a.w, b.w, c.w, d.w);
    }
    if (t == 0) stage[EDGE_N] = make_float4(0.f, 0.f, 0.f, 0.f);

    // accumulators: A = rows{b0,i1,i2,i3} for vnode 2t, Bv for vnode 2t+1
    float2 f0 = ((const float2*)(fin + b0 * V_N))[t];
    float2 f1 = ((const float2*)(fin + i1 * V_N))[t];
    float2 f2 = ((const float2*)(fin + i2 * V_N))[t];
    float2 f3 = ((const float2*)(fin + i3 * V_N))[t];
    float4 A  = make_float4(f0.x, f1.x, f2.x, f3.x);
    float4 Bv = make_float4(f0.y, f1.y, f2.y, f3.y);
    int2 dg = ((const int2*)g_deg)[t];
    int md = max(dg.x, dg.y);

    __syncthreads();

    const ushort2* ellp = (const ushort2*)g_ell;
    #pragma unroll 2
    for (int j = 0; j < md; ++j) {
        ushort2 e = ellp[j * (V_N / 2) + t];
        float4 va = stage[swz(e.x)];
        float4 vb = stage[swz(e.y)];
        A.x  += va.x; A.y  += va.y; A.z  += va.z; A.w  += va.w;
        Bv.x += vb.x; Bv.y += vb.y; Bv.z += vb.z; Bv.w += vb.w;
    }

    ((float2*)(out + b0 * V_N))[t] = make_float2(A.x, Bv.x);
    ((float2*)(out + i1 * V_N))[t] = make_float2(A.y, Bv.y);
    ((float2*)(out + i2 * V_N))[t] = make_float2(A.z, Bv.z);
    ((float2*)(out + i3 * V_N))[t] = make_float2(A.w, Bv.w);
}

extern "C" void kernel_launch(void* const* d_in, const int* in_sizes, int n_in,
                              void* d_out, int out_size) {
    const float* fin   = (const float*)d_in[0];   // [B, V_N]
    const float* fprev = (const float*)d_in[1];   // [B, EDGE_N]
    const float* mask  = (const float*)d_in[2];   // [EDGE_N, V_N]
    int B = in_sizes[0] / V_N;

    static const int kSmem = (EDGE_N + 1) * sizeof(float4);   // 98320 B
    cudaFuncSetAttribute(k_main, cudaFuncAttributeMaxDynamicSharedMemorySize, kSmem);

    k_prep <<<2048, 256>>>((const uint4*)mask);
    k_build<<<(EDGE_N * 32) / 256, 256>>>();
    k_sched<<<1, 128>>>();
    k_main <<<(B + 3) / 4, 512, kSmem>>>(fin, fprev, (float*)d_out, B);
}

// round 17
// speedup vs baseline: 2.1766x; 1.5473x over previous
#include <cuda_runtime.h>
#include <stdint.h>

#define V_N    1024
#define EDGE_N 6144
#define MAXD   64
#define LCAP   24            // scheduler per-column cap (Poisson(6) max ~18)
#define PAD    6176          // floats per staged row (sentinel at 6144); 6176%32==0

// ---- static device scratch (no allocation allowed) ----
__device__ uint16_t g_e2v[EDGE_N];
__device__ __align__(16) int g_deg[V_N];
__device__ __align__(16) uint16_t g_ell[MAXD * V_N];    // vnode-indexed ELL
__device__ __align__(16) uint16_t g_ells[MAXD * V_N];   // slot-indexed ELL
__device__ __align__(16) int g_degs[V_N];               // degree by slot
__device__ __align__(16) uint16_t g_slotOf[V_N];        // vnode -> slot
__device__ __align__(16) uint16_t g_vOfSlot[V_N];       // slot -> vnode

// K1: sentinel-fill ELL, zero degrees, recover edge->vnode from one-hot mask.
__global__ void k_prep(const uint4* __restrict__ mask4) {
    int stride = gridDim.x * blockDim.x;
    int tid0 = blockIdx.x * blockDim.x + threadIdx.x;
    for (int i = tid0; i < MAXD * V_N; i += stride) g_ell[i] = (uint16_t)EDGE_N;
    for (int i = tid0; i < V_N; i += stride) g_deg[i] = 0;
    for (int i = tid0; i < (EDGE_N * V_N) / 4; i += stride) {
        uint4 m = mask4[i];
        if (m.x | m.y | m.z | m.w) {
            int base = i * 4;
            if (m.x) g_e2v[base >> 10]       = (uint16_t)( base      & (V_N - 1));
            if (m.y) g_e2v[(base + 1) >> 10] = (uint16_t)((base + 1) & (V_N - 1));
            if (m.z) g_e2v[(base + 2) >> 10] = (uint16_t)((base + 2) & (V_N - 1));
            if (m.w) g_e2v[(base + 3) >> 10] = (uint16_t)((base + 3) & (V_N - 1));
        }
    }
}

// K2: one WARP per edge: stable deterministic ELL placement, ascending edge order.
__global__ __launch_bounds__(256) void k_build() {
    __shared__ uint16_t se[EDGE_N];
    int t = threadIdx.x;
    const uint32_t* src = (const uint32_t*)g_e2v;
    uint32_t* dst = (uint32_t*)se;
    #pragma unroll
    for (int i = 0; i < EDGE_N / 2 / 256; ++i)
        dst[i * 256 + t] = src[i * 256 + t];
    __syncthreads();

    int e = (blockIdx.x * blockDim.x + t) >> 5;
    int lane = t & 31;
    if (e < EDGE_N) {
        int v = se[e];
        int cnt = 0;
        for (int i = lane; i < e; i += 32) cnt += (se[i] == v);
        cnt = __reduce_add_sync(0xffffffff, cnt);
        if (lane == 0 && cnt < MAXD) {
            g_ell[cnt * V_N + v] = (uint16_t)e;
            atomicAdd(&g_deg[v], 1);
        }
    }
}

// K3: deterministic degree rank (desc) via per-degree bitmask popcount.
// slot = rank: consecutive slots have similar degrees -> per-thread and
// per-warp uniform loop lengths in k_main (kills ELL warp-max padding).
__global__ void k_rank() {                 // 1 block, 1024 threads
    __shared__ unsigned hist[MAXD];
    __shared__ unsigned off[MAXD];
    __shared__ unsigned mask[MAXD][32];
    int v = threadIdx.x;
    if (v < MAXD) hist[v] = 0;
    ((unsigned*)mask)[v] = 0;
    ((unsigned*)mask)[v + 1024] = 0;
    __syncthreads();
    int d = g_deg[v]; if (d > MAXD - 1) d = MAXD - 1;
    atomicAdd(&hist[d], 1);
    atomicOr(&mask[d][v >> 5], 1u << (v & 31));
    __syncthreads();
    if (v == 0) {
        unsigned acc = 0;
        for (int dd = MAXD - 1; dd >= 0; --dd) { off[dd] = acc; acc += hist[dd]; }
    }
    __syncthreads();
    unsigned within = 0;
    int w = v >> 5;
    for (int i = 0; i < w; ++i) within += __popc(mask[d][i]);
    within += __popc(mask[d][w] & ((1u << (v & 31)) - 1u));
    int slot = (int)(off[d] + within);
    g_slotOf[v] = (uint16_t)slot;
    g_vOfSlot[slot] = (uint16_t)v;
}

// K4: build slot-indexed ELL (sentinel-padded) + slot degrees.
__global__ void k_pack2() {               // 1 block, 1024 threads
    int s = threadIdx.x;
    int v = g_vOfSlot[s];
    int d = g_deg[v]; if (d > MAXD) d = MAXD;
    g_degs[s] = d;
    for (int j = 0; j < MAXD; ++j)
        g_ells[j * V_N + s] = (j < d) ? g_ell[j * V_N + v] : (uint16_t)EDGE_N;
}

// K5: warp-cooperative 32-lane bank scheduler (match_any bidding; ran in R14).
// k_main gather instruction (warp w, step j, component k) is a full-warp
// LDS.32 over slots 128w + 4*lane + k; bank = e & 31 (PAD%32==0). Reorder each
// slot's list (fp-add reorder, deterministic) so the 32 lanes of every step
// hit distinct banks. Sentinel (6144) is bank 0 -> reserved once any lane pads.
__global__ __launch_bounds__(1024) void k_sched() {
    __shared__ uint16_t sc[32][32][LCAP];              // 49152 B
    int t = threadIdx.x, W = t >> 5, lane = t & 31;
    int w = W >> 2, k = W & 3;
    int slot = 128 * w + 4 * lane + k;
    int d = g_degs[slot];
    if (__ballot_sync(0xffffffff, d > LCAP)) return;   // warp-uniform fallback

    for (int q = 0; q < d; ++q) sc[W][lane][q] = g_ells[q * V_N + slot];
    int maxd = (int)__reduce_max_sync(0xffffffff, (unsigned)d);

    for (int j = 0; j < maxd; ++j) {
        bool pad = (j >= d);
        unsigned used = __ballot_sync(0xffffffff, pad) ? 1u : 0u;  // bank 0
        bool committed = pad;
        for (int round = 0; round < 4; ++round) {
            if (!__ballot_sync(0xffffffff, !committed)) break;
            int mypos = -1; unsigned mybank = 0; bool forced = false;
            unsigned key = 64 + lane;
            if (!committed) {
                for (int q = j; q < d; ++q) {
                    unsigned b = sc[W][lane][q] & 31u;
                    if (!((used >> b) & 1u)) { mypos = q; mybank = b; break; }
                }
                if (mypos < 0) { forced = true; mypos = j; mybank = sc[W][lane][j] & 31u; }
                key = mybank;
            }
            unsigned peers = __match_any_sync(0xffffffff, key);
            bool leader = ((int)(__ffs(peers) - 1) == lane);
            bool win = !committed && (leader || forced || round == 3);
            unsigned newbits = __reduce_or_sync(0xffffffff, win ? (1u << mybank) : 0u);
            if (win) {
                uint16_t a = sc[W][lane][j];
                sc[W][lane][j] = sc[W][lane][mypos];
                sc[W][lane][mypos] = a;
                committed = true;
            }
            used |= newbits;
        }
    }
    for (int q = 0; q < d; ++q) g_ells[q * V_N + slot] = sc[W][lane][q];
}

// ---- cp.async helpers ----
__device__ __forceinline__ void cp16(uint32_t dst, const float4* src) {
    asm volatile("cp.async.cg.shared.global [%0], [%1], 16;" :: "r"(dst), "l"(src));
}
__device__ __forceinline__ void cp_commit() { asm volatile("cp.async.commit_group;"); }
__device__ __forceinline__ void cp_wait0()  { asm volatile("cp.async.wait_group 0;"); }

// Main: one 256-thread block per FOUR batch rows, 2 blocks/SM. Rows staged
// LINEARLY via cp.async (no STS pass, no register transpose). Thread t owns
// slots 4t..4t+3 (degree-sorted: near-uniform loop lengths). Gather = 16
// bank-scheduled LDS.32 per step. Results bounce through the (now free) stage
// region to restore natural vnode order for fully coalesced output.
__global__ __launch_bounds__(256) void k_main(
    const float* __restrict__ fin, const float* __restrict__ fprev,
    float* __restrict__ out, int B)
{
    extern __shared__ __align__(16) float st[];        // 4*PAD floats = 98816 B
    int t = threadIdx.x;
    uint32_t sbase = (uint32_t)__cvta_generic_to_shared(st);
    long long b0 = (long long)blockIdx.x * 4;
    long long i1 = (b0 + 1 < B) ? b0 + 1 : b0;
    long long i2 = (b0 + 2 < B) ? b0 + 2 : b0;
    long long i3 = (b0 + 3 < B) ? b0 + 3 : b0;
    long long rows[4] = {b0, i1, i2, i3};

    if (t < 4) st[t * PAD + EDGE_N] = 0.0f;            // sentinels (cp.async never writes them)

    #pragma unroll
    for (int r = 0; r < 4; ++r) {
        const float4* src = (const float4*)(fprev + rows[r] * EDGE_N);
        uint32_t dbase = sbase + (uint32_t)(r * PAD) * 4u;
        #pragma unroll
        for (int i = 0; i < 6; ++i) {
            int u = i * 256 + t;
            cp16(dbase + (uint32_t)u * 16u, src + u);
        }
    }
    cp_commit();

    int4 dgs = ((const int4*)g_degs)[t];               // slots 4t..4t+3 (sorted)
    int md = max(max(dgs.x, dgs.y), max(dgs.z, dgs.w));
    ushort4 sl = ((const ushort4*)g_slotOf)[t];        // slots of vnodes 4t..4t+3

    cp_wait0();
    __syncthreads();

    const float* c0 = st;
    const float* c1 = st + PAD;
    const float* c2 = st + 2 * PAD;
    const float* c3 = st + 3 * PAD;
    float a[4][4];                                     // [slot k][row r]
    #pragma unroll
    for (int k = 0; k < 4; ++k)
        #pragma unroll
        for (int r = 0; r < 4; ++r) a[k][r] = 0.0f;

    const ushort4* ellp = (const ushort4*)g_ells;
    for (int j = 0; j < md; ++j) {
        ushort4 e = ellp[j * (V_N / 4) + t];
        a[0][0] += c0[e.x]; a[0][1] += c1[e.x]; a[0][2] += c2[e.x]; a[0][3] += c3[e.x];
        a[1][0] += c0[e.y]; a[1][1] += c1[e.y]; a[1][2] += c2[e.y]; a[1][3] += c3[e.y];
        a[2][0] += c0[e.z]; a[2][1] += c1[e.z]; a[2][2] += c2[e.z]; a[2][3] += c3[e.z];
        a[3][0] += c0[e.w]; a[3][1] += c1[e.w]; a[3][2] += c2[e.w]; a[3][3] += c3[e.w];
    }

    __syncthreads();                                   // all gathers done; stage free
    #pragma unroll
    for (int r = 0; r < 4; ++r) {
        float* resr = st + r * PAD;                    // per-row result plane by slot
        #pragma unroll
        for (int k = 0; k < 4; ++k) resr[4 * t + k] = a[k][r];
    }
    __syncthreads();

    #pragma unroll
    for (int r = 0; r < 4; ++r) {
        const float* resr = st + r * PAD;
        float4 f = ((const float4*)(fin + rows[r] * V_N))[t];
        float4 o = make_float4(resr[sl.x] + f.x, resr[sl.y] + f.y,
                               resr[sl.z] + f.z, resr[sl.w] + f.w);
        ((float4*)(out + rows[r] * V_N))[t] = o;
    }
}

extern "C" void kernel_launch(void* const* d_in, const int* in_sizes, int n_in,
                              void* d_out, int out_size) {
    const float* fin   = (const float*)d_in[0];   // [B, V_N]
    const float* fprev = (const float*)d_in[1];   // [B, EDGE_N]
    const float* mask  = (const float*)d_in[2];   // [EDGE_N, V_N]
    int B = in_sizes[0] / V_N;

    static const int kSmem = 4 * PAD * sizeof(float);   // 98816 B
    cudaFuncSetAttribute(k_main, cudaFuncAttributeMaxDynamicSharedMemorySize, kSmem);

    k_prep <<<2048, 256>>>((const uint4*)mask);
    k_build<<<(EDGE_N * 32) / 256, 256>>>();
    k_rank <<<1, 1024>>>();
    k_pack2<<<1, 1024>>>();
    k_sched<<<1, 1024>>>();
    k_main <<<(B + 3) / 4, 256, kSmem>>>(fin, fprev, (float*)d_out, B);
}